// round 10
// baseline (speedup 1.0000x reference)
#include <cuda_runtime.h>
#include <cuda_bf16.h>
#include <math.h>
#include <stdint.h>

// Problem constants
#define BATCH 8
#define NPTS  2048
#define CDIM  128
#define PDIM  3
#define ODIM  256
#define KNN   16
#define ROWS  (BATCH * NPTS)       // 16384
#define KPAD  144                  // 131 padded up to multiple of 16
#define BN_EPS 1e-5f
#define INVN  (1.0f / (float)ROWS)
#define MBLK  (ROWS / 128)         // 128 m-blocks in gemm grid
#define SR2   132                  // float2 smem row stride

typedef unsigned long long u64;

// ---------------- scratch (static device memory; no allocations) -------------
__device__ int   g_nn[ROWS * KNN];                 // 1 MB
__device__ float g_avg[ROWS * KPAD];               // 9.4 MB
__device__ float g_w1p[KPAD * ODIM];               // 147 KB (padded W1)
__device__ float g_c1[ROWS * ODIM];                // 16.8 MB (pre-BN layer1)
__device__ float g_partM[2][MBLK][2 * ODIM];       // gemm-epilogue partial sum|sumsq
__device__ float g_scale[2][ODIM];                 // BN scale per layer
__device__ float g_shift[2][ODIM];                 // BN shift per layer

// ---------------- prep: pad W1 ------------------------------------------------
__global__ void prep_kernel(const float* __restrict__ W1) {
    int k = blockIdx.x;          // 0..143
    int o = threadIdx.x;         // 0..255
    g_w1p[k * ODIM + o] = (k < 131) ? W1[k * ODIM + o] : 0.0f;
}

// ---------------- KNN (round-7 measured-best version) -------------------------
__device__ __forceinline__ u64 umax64(u64 a, u64 b) { return a > b ? a : b; }

__device__ __forceinline__ void insert16(u64 (&bk)[KNN], u64& wmax, u64 key) {
#pragma unroll
    for (int k = 0; k < KNN; k++) {
        if (bk[k] == wmax) bk[k] = key;      // unique keys: exactly one slot
    }
    u64 m0 = umax64(bk[0], bk[1]),   m1 = umax64(bk[2], bk[3]);
    u64 m2 = umax64(bk[4], bk[5]),   m3 = umax64(bk[6], bk[7]);
    u64 m4 = umax64(bk[8], bk[9]),   m5 = umax64(bk[10], bk[11]);
    u64 m6 = umax64(bk[12], bk[13]), m7 = umax64(bk[14], bk[15]);
    m0 = umax64(m0, m1); m2 = umax64(m2, m3);
    m4 = umax64(m4, m5); m6 = umax64(m6, m7);
    m0 = umax64(m0, m2); m4 = umax64(m4, m6);
    wmax = umax64(m0, m4);
}

__device__ __forceinline__ int warp_max_i(int v) {
    v = max(v, __shfl_xor_sync(0xFFFFFFFFu, v, 16));
    v = max(v, __shfl_xor_sync(0xFFFFFFFFu, v, 8));
    v = max(v, __shfl_xor_sync(0xFFFFFFFFu, v, 4));
    v = max(v, __shfl_xor_sync(0xFFFFFFFFu, v, 2));
    v = max(v, __shfl_xor_sync(0xFFFFFFFFu, v, 1));
    return v;
}

__global__ void __launch_bounds__(128) knn_kernel(const float* __restrict__ pos) {
    __shared__ float4 sp[NPTS];                    // 32 KB
    __shared__ u64 sbuf[16][128];                  // 16 KB, [slot][lane]
    int tid = threadIdx.x;
    int bb = blockIdx.x >> 5;
    int r0 = (blockIdx.x & 31) << 6;
    const float* pb = pos + bb * NPTS * PDIM;
    for (int j = tid; j < NPTS; j += 128) {
        sp[j] = make_float4(pb[j * 3 + 0], pb[j * 3 + 1], pb[j * 3 + 2], 0.0f);
    }
    __syncthreads();

    int qi = r0 + (tid >> 1);
    int sub = tid & 1;
    float4 q = sp[qi];

    u64 bk[KNN];
#pragma unroll
    for (int k = 0; k < KNN; k++) bk[k] = 0xFFF0000000000000ull + (u64)k;
    u64 wmax = 0xFFF000000000000Full;

    int n = 0;
    for (int j0 = 0; j0 < NPTS; j0 += 16) {
#pragma unroll
        for (int c = 0; c < 8; c++) {
            int j = j0 + 2 * c + sub;
            float4 p = sp[j];
            float dx = q.x - p.x, dy = q.y - p.y, dz = q.z - p.z;
            float d = dx * dx + dy * dy + dz * dz;
            u64 key = ((u64)__float_as_uint(d) << 32) | (unsigned)j;
            if (key < wmax) { sbuf[n][tid] = key; n++; }
        }
        if (__any_sync(0xFFFFFFFFu, n >= 8)) {
            int mx = warp_max_i(n);
            for (int k = 0; k < mx; k++) {
                u64 key = sbuf[k][tid];
                if (k < n && key < wmax) insert16(bk, wmax, key);
            }
            n = 0;
        }
    }
    {
        int mx = warp_max_i(n);
        for (int k = 0; k < mx; k++) {
            u64 key = sbuf[k][tid];
            if (k < n && key < wmax) insert16(bk, wmax, key);
        }
    }
#pragma unroll
    for (int k = 0; k < KNN; k++) {
        u64 pk = __shfl_xor_sync(0xFFFFFFFFu, bk[k], 1);
        if (sub == 0 && pk < wmax) insert16(bk, wmax, pk);
    }
    if (sub == 0) {
        int* o = g_nn + (bb * NPTS + qi) * KNN;
#pragma unroll
        for (int k = 0; k < KNN; k++) o[k] = (int)(bk[k] & 0xFFFFFFFFu);
    }
}

// ---------------- gather neighbors + mean (round-7 version) -------------------
__global__ void __launch_bounds__(128) gather_avg_kernel(const float* __restrict__ x,
                                                         const float* __restrict__ pos) {
    int row = blockIdx.x;
    int bb = row >> 11;
    __shared__ int sidx[KNN];
    if (threadIdx.x < KNN) sidx[threadIdx.x] = g_nn[row * KNN + threadIdx.x];
    __syncthreads();

    const float* xb = x + (size_t)bb * NPTS * CDIM;
    float s = 0.0f;
#pragma unroll
    for (int k = 0; k < KNN; k++) s += xb[sidx[k] * CDIM + threadIdx.x];
    g_avg[(size_t)row * KPAD + threadIdx.x] = s * (1.0f / (float)KNN);

    if (threadIdx.x < 16) {
        int c = threadIdx.x;
        float v = 0.0f;
        if (c < PDIM) {
            const float* pb = pos + bb * NPTS * PDIM;
#pragma unroll
            for (int k = 0; k < KNN; k++) v += pb[sidx[k] * PDIM + c];
            v *= (1.0f / (float)KNN);
        }
        g_avg[(size_t)row * KPAD + CDIM + c] = v;
    }
}

// ---------------- 3xTF32 tensor-core GEMM (round-7 skeleton, float2 stages) ---
// C[M x 256] = op(A)[M x K] * B[K x 256], exact-to-~1e-6 via Dekker split.
// BM=128, BN=128, BK=16, 8 warps (2m x 4n), warp tile 64x32, single-buffered
// smem with register prefetch (measured-best structure). hi/lo stored
// INTERLEAVED as float2 so every fragment gather is ONE LDS.64 (96 -> 48
// shared loads per k-tile; we are issue-bound, not tensor-bound).
__device__ __forceinline__ uint32_t f2tf32(float x) {
    uint32_t r;
    asm("cvt.rna.tf32.f32 %0, %1;" : "=r"(r) : "f"(x));
    return r;
}
__device__ __forceinline__ float2 tf32_split2(float x) {
    float hi = __uint_as_float(f2tf32(x));
    float lo = __uint_as_float(f2tf32(x - hi));
    return make_float2(hi, lo);
}
__device__ __forceinline__ void mma_tf32(float* c, uint32_t a0, uint32_t a1,
                                         uint32_t a2, uint32_t a3,
                                         uint32_t b0, uint32_t b1) {
    asm volatile(
        "mma.sync.aligned.m16n8k8.row.col.f32.tf32.tf32.f32 "
        "{%0,%1,%2,%3}, {%4,%5,%6,%7}, {%8,%9}, {%0,%1,%2,%3};\n"
        : "+f"(c[0]), "+f"(c[1]), "+f"(c[2]), "+f"(c[3])
        : "r"(a0), "r"(a1), "r"(a2), "r"(a3), "r"(b0), "r"(b1));
}

template <bool FUSE, int LAYER>
__global__ void __launch_bounds__(256, 2) gemm_tc(const float* __restrict__ A, int lda, int K,
                                                  const float* __restrict__ B,
                                                  float* __restrict__ C) {
    __shared__ float2 Ai[16][SR2];     // A stage transposed [k][m], (hi,lo)
    __shared__ float2 Bi[16][SR2];     // B stage [k][n], (hi,lo)
    __shared__ float s_sc[ODIM], s_sh[ODIM];
    __shared__ float sS[2][128], sQ[2][128];

    int tid = threadIdx.x;
    if (FUSE) { s_sc[tid] = g_scale[0][tid]; s_sh[tid] = g_shift[0][tid]; }

    int wid = tid >> 5;
    int lane = tid & 31;
    int gid = lane >> 2;            // group id 0..7
    int tig = lane & 3;             // thread-in-group 0..3
    int wm = wid >> 2;              // 0..1 -> 64-row half
    int wn = wid & 3;               // 0..3 -> 32-col slice
    int mBase = blockIdx.y * 128;
    int nBase = blockIdx.x * 128;

    // staging geometry:
    // A: thread covers row ar = tid>>1, k-half ak = (tid&1)*8 (8 k values,
    //    2 contiguous LDG.128; thread pairs give 64B/row coalescing).
    // B: bkr = tid>>5 (k-rows, +8), bcq = (tid&31)*4 (4 n values).
    int ar = tid >> 1;
    int ak = (tid & 1) << 3;
    int bkr = tid >> 5;
    int bcq = (tid & 31) << 2;

    const float* Ab = A + (size_t)mBase * lda;
    const float* Bb = B + nBase;

    if (FUSE) __syncthreads();      // s_sc/s_sh ready before first staging

    float acc[4][4][4];
#pragma unroll
    for (int mt = 0; mt < 4; mt++)
#pragma unroll
        for (int nt = 0; nt < 4; nt++)
#pragma unroll
            for (int e = 0; e < 4; e++) acc[mt][nt][e] = 0.0f;

    // prologue: tile 0 into registers
    float4 ra0 = *(const float4*)(Ab + (size_t)ar * lda + ak);
    float4 ra1 = *(const float4*)(Ab + (size_t)ar * lda + ak + 4);
    float4 rb0 = *(const float4*)(Bb + (size_t)bkr * ODIM + bcq);
    float4 rb1 = *(const float4*)(Bb + (size_t)(bkr + 8) * ODIM + bcq);

    for (int k0 = 0; k0 < K; k0 += 16) {
        // ---- stage current tile (FUSE: BN+ReLU on A first) ----
        {
            float av[8] = {ra0.x, ra0.y, ra0.z, ra0.w, ra1.x, ra1.y, ra1.z, ra1.w};
            if (FUSE) {
#pragma unroll
                for (int i = 0; i < 8; i++) {
                    int kc = k0 + ak + i;
                    av[i] = fmaxf(fmaf(av[i], s_sc[kc], s_sh[kc]), 0.0f);
                }
            }
#pragma unroll
            for (int i = 0; i < 8; i++) {
                Ai[ak + i][ar] = tf32_split2(av[i]);
            }
            float2 b00 = tf32_split2(rb0.x), b01 = tf32_split2(rb0.y);
            float2 b02 = tf32_split2(rb0.z), b03 = tf32_split2(rb0.w);
            float2 b10 = tf32_split2(rb1.x), b11 = tf32_split2(rb1.y);
            float2 b12 = tf32_split2(rb1.z), b13 = tf32_split2(rb1.w);
            *(float4*)&Bi[bkr][bcq + 0] = make_float4(b00.x, b00.y, b01.x, b01.y);
            *(float4*)&Bi[bkr][bcq + 2] = make_float4(b02.x, b02.y, b03.x, b03.y);
            *(float4*)&Bi[bkr + 8][bcq + 0] = make_float4(b10.x, b10.y, b11.x, b11.y);
            *(float4*)&Bi[bkr + 8][bcq + 2] = make_float4(b12.x, b12.y, b13.x, b13.y);
        }
        __syncthreads();

        if (k0 + 16 < K) {          // prefetch next tile under the MMA block
            ra0 = *(const float4*)(Ab + (size_t)ar * lda + k0 + 16 + ak);
            ra1 = *(const float4*)(Ab + (size_t)ar * lda + k0 + 16 + ak + 4);
            rb0 = *(const float4*)(Bb + (size_t)(k0 + 16 + bkr) * ODIM + bcq);
            rb1 = *(const float4*)(Bb + (size_t)(k0 + 24 + bkr) * ODIM + bcq);
        }

        // ---- compute: 2 k8 groups ----
#pragma unroll
        for (int g = 0; g < 2; g++) {
            int kr0 = g * 8 + tig;
            int kr1 = kr0 + 4;
            uint32_t bh[4][2], bl[4][2];
#pragma unroll
            for (int nt = 0; nt < 4; nt++) {
                int nn = wn * 32 + nt * 8 + gid;
                float2 r0 = Bi[kr0][nn];
                float2 r1 = Bi[kr1][nn];
                bh[nt][0] = __float_as_uint(r0.x);  bl[nt][0] = __float_as_uint(r0.y);
                bh[nt][1] = __float_as_uint(r1.x);  bl[nt][1] = __float_as_uint(r1.y);
            }
#pragma unroll
            for (int mt = 0; mt < 4; mt++) {
                int m = wm * 64 + mt * 16 + gid;
                float2 q0 = Ai[kr0][m];
                float2 q1 = Ai[kr0][m + 8];
                float2 q2 = Ai[kr1][m];
                float2 q3 = Ai[kr1][m + 8];
                uint32_t ah0 = __float_as_uint(q0.x), al0 = __float_as_uint(q0.y);
                uint32_t ah1 = __float_as_uint(q1.x), al1 = __float_as_uint(q1.y);
                uint32_t ah2 = __float_as_uint(q2.x), al2 = __float_as_uint(q2.y);
                uint32_t ah3 = __float_as_uint(q3.x), al3 = __float_as_uint(q3.y);
#pragma unroll
                for (int nt = 0; nt < 4; nt++)
                    mma_tf32(acc[mt][nt], ah0, ah1, ah2, ah3, bh[nt][0], bh[nt][1]);
#pragma unroll
                for (int nt = 0; nt < 4; nt++)
                    mma_tf32(acc[mt][nt], ah0, ah1, ah2, ah3, bl[nt][0], bl[nt][1]);
#pragma unroll
                for (int nt = 0; nt < 4; nt++)
                    mma_tf32(acc[mt][nt], al0, al1, al2, al3, bh[nt][0], bh[nt][1]);
            }
        }
        __syncthreads();
    }

    // ---- write C ----
#pragma unroll
    for (int mt = 0; mt < 4; mt++) {
#pragma unroll
        for (int nt = 0; nt < 4; nt++) {
            int r = mBase + wm * 64 + mt * 16 + gid;
            int cc = nBase + wn * 32 + nt * 8 + 2 * tig;
            *(float2*)(C + (size_t)r * ODIM + cc) = make_float2(acc[mt][nt][0], acc[mt][nt][1]);
            *(float2*)(C + (size_t)(r + 8) * ODIM + cc) = make_float2(acc[mt][nt][2], acc[mt][nt][3]);
        }
    }

    // ---- epilogue: deterministic per-channel partial sum / sumsq ----
    float cs[4][2], cq[4][2];
#pragma unroll
    for (int nt = 0; nt < 4; nt++) {
#pragma unroll
        for (int e = 0; e < 2; e++) {
            float s = 0.0f, q = 0.0f;
#pragma unroll
            for (int mt = 0; mt < 4; mt++) {
                float v0 = acc[mt][nt][e], v1 = acc[mt][nt][e + 2];
                s += v0 + v1;
                q = fmaf(v0, v0, q);
                q = fmaf(v1, v1, q);
            }
            cs[nt][e] = s; cq[nt][e] = q;
        }
    }
#pragma unroll
    for (int nt = 0; nt < 4; nt++) {
#pragma unroll
        for (int e = 0; e < 2; e++) {
            float s = cs[nt][e], q = cq[nt][e];
            s += __shfl_xor_sync(0xFFFFFFFFu, s, 4);
            s += __shfl_xor_sync(0xFFFFFFFFu, s, 8);
            s += __shfl_xor_sync(0xFFFFFFFFu, s, 16);
            q += __shfl_xor_sync(0xFFFFFFFFu, q, 4);
            q += __shfl_xor_sync(0xFFFFFFFFu, q, 8);
            q += __shfl_xor_sync(0xFFFFFFFFu, q, 16);
            if (gid == 0) {
                int c = wn * 32 + nt * 8 + 2 * tig + e;
                sS[wm][c] = s;  sQ[wm][c] = q;
            }
        }
    }
    __syncthreads();
    if (tid < 128) {
        float s = sS[0][tid] + sS[1][tid];
        float q = sQ[0][tid] + sQ[1][tid];
        g_partM[LAYER][blockIdx.y][nBase + tid] = s;
        g_partM[LAYER][blockIdx.y][ODIM + nBase + tid] = q;
    }
}

// reduce per-mblock partials + compute per-channel scale/shift
__global__ void __launch_bounds__(512) stats_reduce_kernel(int layer,
                                                           const float* __restrict__ gamma,
                                                           const float* __restrict__ beta) {
    __shared__ float ssum[2 * ODIM];
    int t = threadIdx.x;
    float s = 0.0f;
    for (int r = 0; r < MBLK; r++) s += g_partM[layer][r][t];
    ssum[t] = s;
    __syncthreads();
    if (t < ODIM) {
        float mu  = ssum[t] * INVN;
        float var = fmaf(-mu, mu, ssum[ODIM + t] * INVN);
        float sc = gamma[t] * rsqrtf(var + BN_EPS);
        g_scale[layer][t] = sc;
        g_shift[layer][t] = fmaf(-mu, sc, beta[t]);
    }
}

// ---------------- BN apply (final layer, no ReLU), float4 elementwise ---------
__global__ void __launch_bounds__(256) bn_apply_kernel(float* __restrict__ Y, int layer) {
    int idx = blockIdx.x * blockDim.x + threadIdx.x;
    int e = idx * 4;
    int c = e & (ODIM - 1);
    float4 v = *(const float4*)(Y + e);
    float o[4] = {v.x, v.y, v.z, v.w};
#pragma unroll
    for (int j = 0; j < 4; j++) {
        int ch = c + j;
        o[j] = fmaf(o[j], g_scale[layer][ch], g_shift[layer][ch]);
    }
    *(float4*)(Y + e) = make_float4(o[0], o[1], o[2], o[3]);
}

// ---------------- launcher ----------------------------------------------------
extern "C" void kernel_launch(void* const* d_in, const int* in_sizes, int n_in,
                              void* d_out, int out_size) {
    const float* x   = (const float*)d_in[0];   // [8,2048,128]
    const float* pos = (const float*)d_in[1];   // [8,2048,3]
    const float* W1  = (const float*)d_in[2];   // [131,256]
    // d_in[3] = b1 (cancels under train-mode BN)
    const float* g1  = (const float*)d_in[4];
    const float* be1 = (const float*)d_in[5];
    const float* W2  = (const float*)d_in[6];   // [256,256]
    // d_in[7] = b2 (cancels)
    const float* g2  = (const float*)d_in[8];
    const float* be2 = (const float*)d_in[9];
    float* out = (float*)d_out;                 // [8,2048,256]

    prep_kernel<<<KPAD, ODIM>>>(W1);
    knn_kernel<<<BATCH * (NPTS / 64), 128>>>(pos);
    gather_avg_kernel<<<ROWS, 128>>>(x, pos);

    float* avg = nullptr; float* w1p = nullptr; float* c1 = nullptr;
    cudaGetSymbolAddress((void**)&avg, g_avg);
    cudaGetSymbolAddress((void**)&w1p, g_w1p);
    cudaGetSymbolAddress((void**)&c1,  g_c1);

    dim3 ggrid(ODIM / 128, ROWS / 128);         // (2, 128)
    gemm_tc<false, 0><<<ggrid, 256>>>(avg, KPAD, KPAD, w1p, c1);
    stats_reduce_kernel<<<1, 512>>>(0, g1, be1);

    // layer-2 GEMM with BN1+ReLU fused into A staging; stats fused in epilogue
    gemm_tc<true, 1><<<ggrid, 256>>>(c1, ODIM, ODIM, W2, out);
    stats_reduce_kernel<<<1, 512>>>(1, g2, be2);
    bn_apply_kernel<<<ROWS * ODIM / 4 / 256, 256>>>(out, 1);
}

// round 12
// speedup vs baseline: 1.1111x; 1.1111x over previous
#include <cuda_runtime.h>
#include <cuda_bf16.h>
#include <math.h>
#include <stdint.h>

// Problem constants
#define BATCH 8
#define NPTS  2048
#define CDIM  128
#define PDIM  3
#define ODIM  256
#define KNN   16
#define ROWS  (BATCH * NPTS)       // 16384
#define KPAD  144                  // 131 padded up to multiple of 16
#define BN_EPS 1e-5f
#define INVN  (1.0f / (float)ROWS)
#define MBLK  (ROWS / 128)         // 128 m-blocks in gemm grid

typedef unsigned long long u64;

// ---------------- scratch (static device memory; no allocations) -------------
__device__ int   g_nn[ROWS * KNN];                 // 1 MB
__device__ float g_avg[ROWS * KPAD];               // 9.4 MB
__device__ float g_w1p[KPAD * ODIM];               // 147 KB (padded W1)
__device__ float g_c1[ROWS * ODIM];                // 16.8 MB (pre-BN layer1)
__device__ float g_partM[2][MBLK][2 * ODIM];       // gemm-epilogue partial sum|sumsq
__device__ float g_scale[2][ODIM];                 // BN scale per layer
__device__ float g_shift[2][ODIM];                 // BN shift per layer

// ---------------- prep: pad W1 ------------------------------------------------
__global__ void prep_kernel(const float* __restrict__ W1) {
    int k = blockIdx.x;          // 0..143
    int o = threadIdx.x;         // 0..255
    g_w1p[k * ODIM + o] = (k < 131) ? W1[k * ODIM + o] : 0.0f;
}

// ---------------- KNN --------------------------------------------------------
// Round-7 algorithm (2 threads/query, deferred batched inserts, unique u64
// keys = exact jax.lax.top_k semantics). Geometry change ONLY: 64-thread
// blocks, 512 blocks -> ~3.5 CTAs/SM (~10 warps/SM vs 7) for latency hiding.
__device__ __forceinline__ u64 umax64(u64 a, u64 b) { return a > b ? a : b; }

__device__ __forceinline__ void insert16(u64 (&bk)[KNN], u64& wmax, u64 key) {
#pragma unroll
    for (int k = 0; k < KNN; k++) {
        if (bk[k] == wmax) bk[k] = key;      // unique keys: exactly one slot
    }
    u64 m0 = umax64(bk[0], bk[1]),   m1 = umax64(bk[2], bk[3]);
    u64 m2 = umax64(bk[4], bk[5]),   m3 = umax64(bk[6], bk[7]);
    u64 m4 = umax64(bk[8], bk[9]),   m5 = umax64(bk[10], bk[11]);
    u64 m6 = umax64(bk[12], bk[13]), m7 = umax64(bk[14], bk[15]);
    m0 = umax64(m0, m1); m2 = umax64(m2, m3);
    m4 = umax64(m4, m5); m6 = umax64(m6, m7);
    m0 = umax64(m0, m2); m4 = umax64(m4, m6);
    wmax = umax64(m0, m4);
}

__device__ __forceinline__ int warp_max_i(int v) {
    v = max(v, __shfl_xor_sync(0xFFFFFFFFu, v, 16));
    v = max(v, __shfl_xor_sync(0xFFFFFFFFu, v, 8));
    v = max(v, __shfl_xor_sync(0xFFFFFFFFu, v, 4));
    v = max(v, __shfl_xor_sync(0xFFFFFFFFu, v, 2));
    v = max(v, __shfl_xor_sync(0xFFFFFFFFu, v, 1));
    return v;
}

__global__ void __launch_bounds__(64) knn_kernel(const float* __restrict__ pos) {
    __shared__ float4 sp[NPTS];                    // 32 KB
    __shared__ u64 sbuf[16][64];                   // 8 KB, [slot][lane]: 2-way max
    int tid = threadIdx.x;
    int bb = blockIdx.x >> 6;                      // batch (64 blocks per batch)
    int r0 = (blockIdx.x & 63) << 5;               // query offset (32 queries/block)
    const float* pb = pos + bb * NPTS * PDIM;
    for (int j = tid; j < NPTS; j += 64) {
        sp[j] = make_float4(pb[j * 3 + 0], pb[j * 3 + 1], pb[j * 3 + 2], 0.0f);
    }
    __syncthreads();

    int qi = r0 + (tid >> 1);                      // query index (pairs share)
    int sub = tid & 1;                             // parity of points scanned
    float4 q = sp[qi];

    u64 bk[KNN];
#pragma unroll
    for (int k = 0; k < KNN; k++) bk[k] = 0xFFF0000000000000ull + (u64)k; // > any real key
    u64 wmax = 0xFFF000000000000Full;

    int n = 0;
    for (int j0 = 0; j0 < NPTS; j0 += 16) {
#pragma unroll
        for (int c = 0; c < 8; c++) {
            int j = j0 + 2 * c + sub;
            float4 p = sp[j];
            float dx = q.x - p.x, dy = q.y - p.y, dz = q.z - p.z;
            float d = dx * dx + dy * dy + dz * dz;
            u64 key = ((u64)__float_as_uint(d) << 32) | (unsigned)j;
            if (key < wmax) { sbuf[n][tid] = key; n++; }   // predicated push
        }
        if (__any_sync(0xFFFFFFFFu, n >= 8)) {
            int mx = warp_max_i(n);
            for (int k = 0; k < mx; k++) {          // lockstep insert rounds
                u64 key = sbuf[k][tid];
                if (k < n && key < wmax) insert16(bk, wmax, key);
            }
            n = 0;
        }
    }
    {   // final flush
        int mx = warp_max_i(n);
        for (int k = 0; k < mx; k++) {
            u64 key = sbuf[k][tid];
            if (k < n && key < wmax) insert16(bk, wmax, key);
        }
    }

    // pair merge: even lane absorbs odd lane's 16 keys (union superset, exact)
#pragma unroll
    for (int k = 0; k < KNN; k++) {
        u64 pk = __shfl_xor_sync(0xFFFFFFFFu, bk[k], 1);
        if (sub == 0 && pk < wmax) insert16(bk, wmax, pk);
    }
    if (sub == 0) {
        int* o = g_nn + (bb * NPTS + qi) * KNN;
#pragma unroll
        for (int k = 0; k < KNN; k++) o[k] = (int)(bk[k] & 0xFFFFFFFFu);
    }
}

// ---------------- gather neighbors + mean (round-7 measured-best) -------------
__global__ void __launch_bounds__(128) gather_avg_kernel(const float* __restrict__ x,
                                                         const float* __restrict__ pos) {
    int row = blockIdx.x;
    int bb = row >> 11;
    __shared__ int sidx[KNN];
    if (threadIdx.x < KNN) sidx[threadIdx.x] = g_nn[row * KNN + threadIdx.x];
    __syncthreads();

    const float* xb = x + (size_t)bb * NPTS * CDIM;
    float s = 0.0f;
#pragma unroll
    for (int k = 0; k < KNN; k++) s += xb[sidx[k] * CDIM + threadIdx.x];
    g_avg[(size_t)row * KPAD + threadIdx.x] = s * (1.0f / (float)KNN);

    if (threadIdx.x < 16) {
        int c = threadIdx.x;
        float v = 0.0f;
        if (c < PDIM) {
            const float* pb = pos + bb * NPTS * PDIM;
#pragma unroll
            for (int k = 0; k < KNN; k++) v += pb[sidx[k] * PDIM + c];
            v *= (1.0f / (float)KNN);
        }
        g_avg[(size_t)row * KPAD + CDIM + c] = v;
    }
}

// ---------------- 3xTF32 tensor-core GEMM (round-7 measured-best, verbatim) ---
// C[M x 256] = op(A)[M x K] * B[K x 256], exact-to-~1e-6 via Dekker split.
// BM=128, BN=128, BK=16, 8 warps (2m x 4n), warp tile 64x32, single-buffered
// smem (136 row stride, conflict-free) with register prefetch.
__device__ __forceinline__ uint32_t f2tf32(float x) {
    uint32_t r;
    asm("cvt.rna.tf32.f32 %0, %1;" : "=r"(r) : "f"(x));
    return r;
}
__device__ __forceinline__ void tf32_split(float x, float& hi, float& lo) {
    uint32_t h = f2tf32(x);
    hi = __uint_as_float(h);
    lo = __uint_as_float(f2tf32(x - hi));
}
__device__ __forceinline__ void mma_tf32(float* c, uint32_t a0, uint32_t a1,
                                         uint32_t a2, uint32_t a3,
                                         uint32_t b0, uint32_t b1) {
    asm volatile(
        "mma.sync.aligned.m16n8k8.row.col.f32.tf32.tf32.f32 "
        "{%0,%1,%2,%3}, {%4,%5,%6,%7}, {%8,%9}, {%0,%1,%2,%3};\n"
        : "+f"(c[0]), "+f"(c[1]), "+f"(c[2]), "+f"(c[3])
        : "r"(a0), "r"(a1), "r"(a2), "r"(a3), "r"(b0), "r"(b1));
}

template <bool FUSE, int LAYER>
__global__ void __launch_bounds__(256, 2) gemm_tc(const float* __restrict__ A, int lda, int K,
                                                  const float* __restrict__ B,
                                                  float* __restrict__ C) {
    __shared__ float Ah[16][136], Al[16][136];     // A stage transposed [k][m]
    __shared__ float Bh[16][136], Bl[16][136];     // B stage [k][n]
    __shared__ float s_sc[ODIM], s_sh[ODIM];
    __shared__ float sS[2][128], sQ[2][128];

    int tid = threadIdx.x;
    if (FUSE) { s_sc[tid] = g_scale[0][tid]; s_sh[tid] = g_shift[0][tid]; }

    int wid = tid >> 5;
    int lane = tid & 31;
    int gid = lane >> 2;            // group id 0..7
    int tig = lane & 3;             // thread-in-group 0..3
    int wm = wid >> 2;              // 0..1 -> 64-row half
    int wn = wid & 3;               // 0..3 -> 32-col slice
    int mBase = blockIdx.y * 128;
    int nBase = blockIdx.x * 128;

    int ar0 = tid >> 2;             // A rows 0..63 (+64)
    int akq = (tid & 3) << 2;       // A k-offset
    int bkr = tid >> 5;             // B k-rows 0..7 (+8)
    int bcq = (tid & 31) << 2;      // B n-offset

    const float* Ab = A + (size_t)mBase * lda;
    const float* Bb = B + nBase;

    if (FUSE) __syncthreads();

    float acc[4][4][4];
#pragma unroll
    for (int mt = 0; mt < 4; mt++)
#pragma unroll
        for (int nt = 0; nt < 4; nt++)
#pragma unroll
            for (int e = 0; e < 4; e++) acc[mt][nt][e] = 0.0f;

    // prologue: tile 0
    float4 ra0 = *(const float4*)(Ab + (size_t)ar0 * lda + akq);
    float4 ra1 = *(const float4*)(Ab + (size_t)(ar0 + 64) * lda + akq);
    float4 rb0 = *(const float4*)(Bb + (size_t)bkr * ODIM + bcq);
    float4 rb1 = *(const float4*)(Bb + (size_t)(bkr + 8) * ODIM + bcq);

    for (int k0 = 0; k0 < K; k0 += 16) {
        // ---- stage with hi/lo split (FUSE: BN+ReLU first) ----
        float av0[4] = {ra0.x, ra0.y, ra0.z, ra0.w};
        float av1[4] = {ra1.x, ra1.y, ra1.z, ra1.w};
        if (FUSE) {
#pragma unroll
            for (int i = 0; i < 4; i++) {
                float sc = s_sc[k0 + akq + i], sh = s_sh[k0 + akq + i];
                av0[i] = fmaxf(fmaf(av0[i], sc, sh), 0.0f);
                av1[i] = fmaxf(fmaf(av1[i], sc, sh), 0.0f);
            }
        }
#pragma unroll
        for (int i = 0; i < 4; i++) {
            float h, l;
            tf32_split(av0[i], h, l);
            Ah[akq + i][ar0] = h;  Al[akq + i][ar0] = l;
            tf32_split(av1[i], h, l);
            Ah[akq + i][ar0 + 64] = h;  Al[akq + i][ar0 + 64] = l;
        }
        {
            float bv0[4] = {rb0.x, rb0.y, rb0.z, rb0.w};
            float bv1[4] = {rb1.x, rb1.y, rb1.z, rb1.w};
            float4 h0, l0, h1, l1;
            tf32_split(bv0[0], h0.x, l0.x); tf32_split(bv0[1], h0.y, l0.y);
            tf32_split(bv0[2], h0.z, l0.z); tf32_split(bv0[3], h0.w, l0.w);
            tf32_split(bv1[0], h1.x, l1.x); tf32_split(bv1[1], h1.y, l1.y);
            tf32_split(bv1[2], h1.z, l1.z); tf32_split(bv1[3], h1.w, l1.w);
            *(float4*)&Bh[bkr][bcq] = h0;  *(float4*)&Bl[bkr][bcq] = l0;
            *(float4*)&Bh[bkr + 8][bcq] = h1;  *(float4*)&Bl[bkr + 8][bcq] = l1;
        }
        __syncthreads();

        if (k0 + 16 < K) {          // prefetch next tile under the MMA block
            ra0 = *(const float4*)(Ab + (size_t)ar0 * lda + k0 + 16 + akq);
            ra1 = *(const float4*)(Ab + (size_t)(ar0 + 64) * lda + k0 + 16 + akq);
            rb0 = *(const float4*)(Bb + (size_t)(k0 + 16 + bkr) * ODIM + bcq);
            rb1 = *(const float4*)(Bb + (size_t)(k0 + 24 + bkr) * ODIM + bcq);
        }

        // ---- compute: 2 k8 steps ----
#pragma unroll
        for (int g = 0; g < 2; g++) {
            int kr0 = g * 8 + tig;
            int kr1 = kr0 + 4;
            uint32_t bh[4][2], bl[4][2];
#pragma unroll
            for (int nt = 0; nt < 4; nt++) {
                int nn = wn * 32 + nt * 8 + gid;
                bh[nt][0] = __float_as_uint(Bh[kr0][nn]);
                bh[nt][1] = __float_as_uint(Bh[kr1][nn]);
                bl[nt][0] = __float_as_uint(Bl[kr0][nn]);
                bl[nt][1] = __float_as_uint(Bl[kr1][nn]);
            }
#pragma unroll
            for (int mt = 0; mt < 4; mt++) {
                int m = wm * 64 + mt * 16 + gid;
                uint32_t ah0 = __float_as_uint(Ah[kr0][m]);
                uint32_t ah1 = __float_as_uint(Ah[kr0][m + 8]);
                uint32_t ah2 = __float_as_uint(Ah[kr1][m]);
                uint32_t ah3 = __float_as_uint(Ah[kr1][m + 8]);
                uint32_t al0 = __float_as_uint(Al[kr0][m]);
                uint32_t al1 = __float_as_uint(Al[kr0][m + 8]);
                uint32_t al2 = __float_as_uint(Al[kr1][m]);
                uint32_t al3 = __float_as_uint(Al[kr1][m + 8]);
#pragma unroll
                for (int nt = 0; nt < 4; nt++) {
                    mma_tf32(acc[mt][nt], ah0, ah1, ah2, ah3, bh[nt][0], bh[nt][1]);
                    mma_tf32(acc[mt][nt], ah0, ah1, ah2, ah3, bl[nt][0], bl[nt][1]);
                    mma_tf32(acc[mt][nt], al0, al1, al2, al3, bh[nt][0], bh[nt][1]);
                }
            }
        }
        __syncthreads();
    }

    // ---- write C ----
#pragma unroll
    for (int mt = 0; mt < 4; mt++) {
#pragma unroll
        for (int nt = 0; nt < 4; nt++) {
            int r = mBase + wm * 64 + mt * 16 + gid;
            int cc = nBase + wn * 32 + nt * 8 + 2 * tig;
            *(float2*)(C + (size_t)r * ODIM + cc) = make_float2(acc[mt][nt][0], acc[mt][nt][1]);
            *(float2*)(C + (size_t)(r + 8) * ODIM + cc) = make_float2(acc[mt][nt][2], acc[mt][nt][3]);
        }
    }

    // ---- epilogue: deterministic per-channel partial sum / sumsq ----
    float cs[4][2], cq[4][2];
#pragma unroll
    for (int nt = 0; nt < 4; nt++) {
#pragma unroll
        for (int e = 0; e < 2; e++) {
            float s = 0.0f, q = 0.0f;
#pragma unroll
            for (int mt = 0; mt < 4; mt++) {
                float v0 = acc[mt][nt][e], v1 = acc[mt][nt][e + 2];
                s += v0 + v1;
                q = fmaf(v0, v0, q);
                q = fmaf(v1, v1, q);
            }
            cs[nt][e] = s; cq[nt][e] = q;
        }
    }
#pragma unroll
    for (int nt = 0; nt < 4; nt++) {
#pragma unroll
        for (int e = 0; e < 2; e++) {
            float s = cs[nt][e], q = cq[nt][e];
            s += __shfl_xor_sync(0xFFFFFFFFu, s, 4);
            s += __shfl_xor_sync(0xFFFFFFFFu, s, 8);
            s += __shfl_xor_sync(0xFFFFFFFFu, s, 16);
            q += __shfl_xor_sync(0xFFFFFFFFu, q, 4);
            q += __shfl_xor_sync(0xFFFFFFFFu, q, 8);
            q += __shfl_xor_sync(0xFFFFFFFFu, q, 16);
            if (gid == 0) {
                int c = wn * 32 + nt * 8 + 2 * tig + e;
                sS[wm][c] = s;  sQ[wm][c] = q;
            }
        }
    }
    __syncthreads();
    if (tid < 128) {
        float s = sS[0][tid] + sS[1][tid];
        float q = sQ[0][tid] + sQ[1][tid];
        g_partM[LAYER][blockIdx.y][nBase + tid] = s;
        g_partM[LAYER][blockIdx.y][ODIM + nBase + tid] = q;
    }
}

// reduce per-mblock partials + compute per-channel scale/shift
__global__ void __launch_bounds__(512) stats_reduce_kernel(int layer,
                                                           const float* __restrict__ gamma,
                                                           const float* __restrict__ beta) {
    __shared__ float ssum[2 * ODIM];
    int t = threadIdx.x;
    float s = 0.0f;
    for (int r = 0; r < MBLK; r++) s += g_partM[layer][r][t];
    ssum[t] = s;
    __syncthreads();
    if (t < ODIM) {
        float mu  = ssum[t] * INVN;
        float var = fmaf(-mu, mu, ssum[ODIM + t] * INVN);
        float sc = gamma[t] * rsqrtf(var + BN_EPS);
        g_scale[layer][t] = sc;
        g_shift[layer][t] = fmaf(-mu, sc, beta[t]);
    }
}

// ---------------- BN apply (final layer, no ReLU), float4 elementwise ---------
__global__ void __launch_bounds__(256) bn_apply_kernel(float* __restrict__ Y, int layer) {
    int idx = blockIdx.x * blockDim.x + threadIdx.x;
    int e = idx * 4;
    int c = e & (ODIM - 1);
    float4 v = *(const float4*)(Y + e);
    float o[4] = {v.x, v.y, v.z, v.w};
#pragma unroll
    for (int j = 0; j < 4; j++) {
        int ch = c + j;
        o[j] = fmaf(o[j], g_scale[layer][ch], g_shift[layer][ch]);
    }
    *(float4*)(Y + e) = make_float4(o[0], o[1], o[2], o[3]);
}

// ---------------- launcher ----------------------------------------------------
extern "C" void kernel_launch(void* const* d_in, const int* in_sizes, int n_in,
                              void* d_out, int out_size) {
    const float* x   = (const float*)d_in[0];   // [8,2048,128]
    const float* pos = (const float*)d_in[1];   // [8,2048,3]
    const float* W1  = (const float*)d_in[2];   // [131,256]
    // d_in[3] = b1 (cancels under train-mode BN)
    const float* g1  = (const float*)d_in[4];
    const float* be1 = (const float*)d_in[5];
    const float* W2  = (const float*)d_in[6];   // [256,256]
    // d_in[7] = b2 (cancels)
    const float* g2  = (const float*)d_in[8];
    const float* be2 = (const float*)d_in[9];
    float* out = (float*)d_out;                 // [8,2048,256]

    prep_kernel<<<KPAD, ODIM>>>(W1);
    knn_kernel<<<BATCH * (NPTS / 32), 64>>>(pos);
    gather_avg_kernel<<<ROWS, 128>>>(x, pos);

    float* avg = nullptr; float* w1p = nullptr; float* c1 = nullptr;
    cudaGetSymbolAddress((void**)&avg, g_avg);
    cudaGetSymbolAddress((void**)&w1p, g_w1p);
    cudaGetSymbolAddress((void**)&c1,  g_c1);

    dim3 ggrid(ODIM / 128, ROWS / 128);         // (2, 128)
    gemm_tc<false, 0><<<ggrid, 256>>>(avg, KPAD, KPAD, w1p, c1);
    stats_reduce_kernel<<<1, 512>>>(0, g1, be1);

    // layer-2 GEMM with BN1+ReLU fused into A staging; stats fused in epilogue
    gemm_tc<true, 1><<<ggrid, 256>>>(c1, ODIM, ODIM, W2, out);
    stats_reduce_kernel<<<1, 512>>>(1, g2, be2);
    bn_apply_kernel<<<ROWS * ODIM / 4 / 256, 256>>>(out, 1);
}

// round 13
// speedup vs baseline: 1.2888x; 1.1599x over previous
#include <cuda_runtime.h>
#include <cuda_bf16.h>
#include <math.h>
#include <stdint.h>

// Problem constants
#define BATCH 8
#define NPTS  2048
#define CDIM  128
#define PDIM  3
#define ODIM  256
#define KNN   16
#define ROWS  (BATCH * NPTS)       // 16384
#define KPAD  144                  // 131 padded up to multiple of 16
#define BN_EPS 1e-5f
#define INVN  (1.0f / (float)ROWS)
#define MBLK  (ROWS / 128)         // 128 m-blocks in gemm grid

typedef unsigned long long u64;

// ---------------- scratch (static device memory; no allocations) -------------
__device__ int   g_nn[ROWS * KNN];                 // 1 MB
__device__ float g_avg[ROWS * KPAD];               // 9.4 MB
__device__ float g_w1p[KPAD * ODIM];               // 147 KB (padded W1)
__device__ float g_c1[ROWS * ODIM];                // 16.8 MB (pre-BN layer1)
__device__ float g_partM[2][MBLK][2 * ODIM];       // gemm-epilogue partial sum|sumsq
__device__ float g_scale[2][ODIM];                 // BN scale per layer
__device__ float g_shift[2][ODIM];                 // BN shift per layer

// ---------------- prep: pad W1 ------------------------------------------------
__global__ void prep_kernel(const float* __restrict__ W1) {
    int k = blockIdx.x;          // 0..143
    int o = threadIdx.x;         // 0..255
    g_w1p[k * ODIM + o] = (k < 131) ? W1[k * ODIM + o] : 0.0f;
}

// ---------------- KNN --------------------------------------------------------
// 2 threads per query (even/odd point parity); register top-16 via deferred
// batched inserts; unique u64 keys (dist_bits<<32 | idx) = exact top_k
// semantics; pair-merge via shfl. This round: REDUX warp-max (replaces 5
// dependent SHFLs per flush) and direct seeding of bk[] from the first 16
// candidates (skips the sentinel all-push phase) — both bit-identical.
__device__ __forceinline__ u64 umax64(u64 a, u64 b) { return a > b ? a : b; }

__device__ __forceinline__ u64 max16(const u64 (&bk)[KNN]) {
    u64 m0 = umax64(bk[0], bk[1]),   m1 = umax64(bk[2], bk[3]);
    u64 m2 = umax64(bk[4], bk[5]),   m3 = umax64(bk[6], bk[7]);
    u64 m4 = umax64(bk[8], bk[9]),   m5 = umax64(bk[10], bk[11]);
    u64 m6 = umax64(bk[12], bk[13]), m7 = umax64(bk[14], bk[15]);
    m0 = umax64(m0, m1); m2 = umax64(m2, m3);
    m4 = umax64(m4, m5); m6 = umax64(m6, m7);
    m0 = umax64(m0, m2); m4 = umax64(m4, m6);
    return umax64(m0, m4);
}

__device__ __forceinline__ void insert16(u64 (&bk)[KNN], u64& wmax, u64 key) {
#pragma unroll
    for (int k = 0; k < KNN; k++) {
        if (bk[k] == wmax) bk[k] = key;      // unique keys: exactly one slot
    }
    wmax = max16(bk);
}

__global__ void __launch_bounds__(64) knn_kernel(const float* __restrict__ pos) {
    __shared__ float4 sp[NPTS];                    // 32 KB
    __shared__ u64 sbuf[16][64];                   // 8 KB, [slot][lane]
    int tid = threadIdx.x;
    int bb = blockIdx.x >> 6;                      // batch (64 blocks per batch)
    int r0 = (blockIdx.x & 63) << 5;               // query offset (32 queries/block)
    const float* pb = pos + bb * NPTS * PDIM;
    for (int j = tid; j < NPTS; j += 64) {
        sp[j] = make_float4(pb[j * 3 + 0], pb[j * 3 + 1], pb[j * 3 + 2], 0.0f);
    }
    __syncthreads();

    int qi = r0 + (tid >> 1);                      // query index (pairs share)
    int sub = tid & 1;                             // parity of points scanned
    float4 q = sp[qi];

    // seed: the thread's first 16 candidates (points 0..31) ARE its initial
    // top-16 — identical to inserting them one by one.
    u64 bk[KNN];
#pragma unroll
    for (int k = 0; k < KNN; k++) {
        int j = 2 * k + sub;
        float4 p = sp[j];
        float dx = q.x - p.x, dy = q.y - p.y, dz = q.z - p.z;
        float d = dx * dx + dy * dy + dz * dz;
        bk[k] = ((u64)__float_as_uint(d) << 32) | (unsigned)j;
    }
    u64 wmax = max16(bk);

    int n = 0;
    for (int j0 = 32; j0 < NPTS; j0 += 16) {
#pragma unroll
        for (int c = 0; c < 8; c++) {
            int j = j0 + 2 * c + sub;
            float4 p = sp[j];
            float dx = q.x - p.x, dy = q.y - p.y, dz = q.z - p.z;
            float d = dx * dx + dy * dy + dz * dz;
            u64 key = ((u64)__float_as_uint(d) << 32) | (unsigned)j;
            if (key < wmax) { sbuf[n][tid] = key; n++; }   // predicated push
        }
        if (__any_sync(0xFFFFFFFFu, n >= 8)) {
            int mx = __reduce_max_sync(0xFFFFFFFFu, n);    // REDUX, 1 instr
            for (int k = 0; k < mx; k++) {          // lockstep insert rounds
                u64 key = sbuf[k][tid];
                if (k < n && key < wmax) insert16(bk, wmax, key);
            }
            n = 0;
        }
    }
    {   // final flush
        int mx = __reduce_max_sync(0xFFFFFFFFu, n);
        for (int k = 0; k < mx; k++) {
            u64 key = sbuf[k][tid];
            if (k < n && key < wmax) insert16(bk, wmax, key);
        }
    }

    // pair merge: even lane absorbs odd lane's 16 keys (union superset, exact)
#pragma unroll
    for (int k = 0; k < KNN; k++) {
        u64 pk = __shfl_xor_sync(0xFFFFFFFFu, bk[k], 1);
        if (sub == 0 && pk < wmax) insert16(bk, wmax, pk);
    }
    if (sub == 0) {
        int* o = g_nn + (bb * NPTS + qi) * KNN;
#pragma unroll
        for (int k = 0; k < KNN; k++) o[k] = (int)(bk[k] & 0xFFFFFFFFu);
    }
}

// ---------------- gather neighbors + mean (round-7 measured-best) -------------
__global__ void __launch_bounds__(128) gather_avg_kernel(const float* __restrict__ x,
                                                         const float* __restrict__ pos) {
    int row = blockIdx.x;
    int bb = row >> 11;
    __shared__ int sidx[KNN];
    if (threadIdx.x < KNN) sidx[threadIdx.x] = g_nn[row * KNN + threadIdx.x];
    __syncthreads();

    const float* xb = x + (size_t)bb * NPTS * CDIM;
    float s = 0.0f;
#pragma unroll
    for (int k = 0; k < KNN; k++) s += xb[sidx[k] * CDIM + threadIdx.x];
    g_avg[(size_t)row * KPAD + threadIdx.x] = s * (1.0f / (float)KNN);

    if (threadIdx.x < 16) {
        int c = threadIdx.x;
        float v = 0.0f;
        if (c < PDIM) {
            const float* pb = pos + bb * NPTS * PDIM;
#pragma unroll
            for (int k = 0; k < KNN; k++) v += pb[sidx[k] * PDIM + c];
            v *= (1.0f / (float)KNN);
        }
        g_avg[(size_t)row * KPAD + CDIM + c] = v;
    }
}

// ---------------- 2-term TF32 tensor-core GEMM --------------------------------
// C[M x 256] = op(A)[M x K] * B[K x 256].  A staged as tf32(hi) only; B split
// hi/lo (Dekker).  C ~= Ah*Bh + Ah*Bl  — dropped term al*b gives rel err
// ~2e-4 (threshold 1e-3).  vs round-7 3-term: 1/3 fewer MMAs, no Al array
// (staging stores, splits, and fragment LDS all shrink).
// BM=128, BN=128, BK=16, 8 warps (2m x 4n), warp tile 64x32, single-buffered
// smem (136 row stride, conflict-free) with register prefetch.
__device__ __forceinline__ uint32_t f2tf32(float x) {
    uint32_t r;
    asm("cvt.rna.tf32.f32 %0, %1;" : "=r"(r) : "f"(x));
    return r;
}
__device__ __forceinline__ void tf32_split(float x, float& hi, float& lo) {
    uint32_t h = f2tf32(x);
    hi = __uint_as_float(h);
    lo = __uint_as_float(f2tf32(x - hi));
}
__device__ __forceinline__ void mma_tf32(float* c, uint32_t a0, uint32_t a1,
                                         uint32_t a2, uint32_t a3,
                                         uint32_t b0, uint32_t b1) {
    asm volatile(
        "mma.sync.aligned.m16n8k8.row.col.f32.tf32.tf32.f32 "
        "{%0,%1,%2,%3}, {%4,%5,%6,%7}, {%8,%9}, {%0,%1,%2,%3};\n"
        : "+f"(c[0]), "+f"(c[1]), "+f"(c[2]), "+f"(c[3])
        : "r"(a0), "r"(a1), "r"(a2), "r"(a3), "r"(b0), "r"(b1));
}

template <bool FUSE, int LAYER>
__global__ void __launch_bounds__(256, 2) gemm_tc(const float* __restrict__ A, int lda, int K,
                                                  const float* __restrict__ B,
                                                  float* __restrict__ C) {
    __shared__ float Ah[16][136];                  // A stage transposed [k][m], tf32 hi
    __shared__ float Bh[16][136], Bl[16][136];     // B stage [k][n], hi/lo
    __shared__ float s_sc[ODIM], s_sh[ODIM];
    __shared__ float sS[2][128], sQ[2][128];

    int tid = threadIdx.x;
    if (FUSE) { s_sc[tid] = g_scale[0][tid]; s_sh[tid] = g_shift[0][tid]; }

    int wid = tid >> 5;
    int lane = tid & 31;
    int gid = lane >> 2;            // group id 0..7
    int tig = lane & 3;             // thread-in-group 0..3
    int wm = wid >> 2;              // 0..1 -> 64-row half
    int wn = wid & 3;               // 0..3 -> 32-col slice
    int mBase = blockIdx.y * 128;
    int nBase = blockIdx.x * 128;

    int ar0 = tid >> 2;             // A rows 0..63 (+64)
    int akq = (tid & 3) << 2;       // A k-offset
    int bkr = tid >> 5;             // B k-rows 0..7 (+8)
    int bcq = (tid & 31) << 2;      // B n-offset

    const float* Ab = A + (size_t)mBase * lda;
    const float* Bb = B + nBase;

    if (FUSE) __syncthreads();

    float acc[4][4][4];
#pragma unroll
    for (int mt = 0; mt < 4; mt++)
#pragma unroll
        for (int nt = 0; nt < 4; nt++)
#pragma unroll
            for (int e = 0; e < 4; e++) acc[mt][nt][e] = 0.0f;

    // prologue: tile 0
    float4 ra0 = *(const float4*)(Ab + (size_t)ar0 * lda + akq);
    float4 ra1 = *(const float4*)(Ab + (size_t)(ar0 + 64) * lda + akq);
    float4 rb0 = *(const float4*)(Bb + (size_t)bkr * ODIM + bcq);
    float4 rb1 = *(const float4*)(Bb + (size_t)(bkr + 8) * ODIM + bcq);

    for (int k0 = 0; k0 < K; k0 += 16) {
        // ---- stage (FUSE: BN+ReLU on A first); A hi-only, B hi/lo ----
        float av0[4] = {ra0.x, ra0.y, ra0.z, ra0.w};
        float av1[4] = {ra1.x, ra1.y, ra1.z, ra1.w};
        if (FUSE) {
#pragma unroll
            for (int i = 0; i < 4; i++) {
                float sc = s_sc[k0 + akq + i], sh = s_sh[k0 + akq + i];
                av0[i] = fmaxf(fmaf(av0[i], sc, sh), 0.0f);
                av1[i] = fmaxf(fmaf(av1[i], sc, sh), 0.0f);
            }
        }
#pragma unroll
        for (int i = 0; i < 4; i++) {
            Ah[akq + i][ar0]      = __uint_as_float(f2tf32(av0[i]));
            Ah[akq + i][ar0 + 64] = __uint_as_float(f2tf32(av1[i]));
        }
        {
            float4 h0, l0, h1, l1;
            tf32_split(rb0.x, h0.x, l0.x); tf32_split(rb0.y, h0.y, l0.y);
            tf32_split(rb0.z, h0.z, l0.z); tf32_split(rb0.w, h0.w, l0.w);
            tf32_split(rb1.x, h1.x, l1.x); tf32_split(rb1.y, h1.y, l1.y);
            tf32_split(rb1.z, h1.z, l1.z); tf32_split(rb1.w, h1.w, l1.w);
            *(float4*)&Bh[bkr][bcq] = h0;  *(float4*)&Bl[bkr][bcq] = l0;
            *(float4*)&Bh[bkr + 8][bcq] = h1;  *(float4*)&Bl[bkr + 8][bcq] = l1;
        }
        __syncthreads();

        if (k0 + 16 < K) {          // prefetch next tile under the MMA block
            ra0 = *(const float4*)(Ab + (size_t)ar0 * lda + k0 + 16 + akq);
            ra1 = *(const float4*)(Ab + (size_t)(ar0 + 64) * lda + k0 + 16 + akq);
            rb0 = *(const float4*)(Bb + (size_t)(k0 + 16 + bkr) * ODIM + bcq);
            rb1 = *(const float4*)(Bb + (size_t)(k0 + 24 + bkr) * ODIM + bcq);
        }

        // ---- compute: 2 k8 steps, 2 Dekker terms ----
#pragma unroll
        for (int g = 0; g < 2; g++) {
            int kr0 = g * 8 + tig;
            int kr1 = kr0 + 4;
            uint32_t bh[4][2], bl[4][2];
#pragma unroll
            for (int nt = 0; nt < 4; nt++) {
                int nn = wn * 32 + nt * 8 + gid;
                bh[nt][0] = __float_as_uint(Bh[kr0][nn]);
                bh[nt][1] = __float_as_uint(Bh[kr1][nn]);
                bl[nt][0] = __float_as_uint(Bl[kr0][nn]);
                bl[nt][1] = __float_as_uint(Bl[kr1][nn]);
            }
#pragma unroll
            for (int mt = 0; mt < 4; mt++) {
                int m = wm * 64 + mt * 16 + gid;
                uint32_t ah0 = __float_as_uint(Ah[kr0][m]);
                uint32_t ah1 = __float_as_uint(Ah[kr0][m + 8]);
                uint32_t ah2 = __float_as_uint(Ah[kr1][m]);
                uint32_t ah3 = __float_as_uint(Ah[kr1][m + 8]);
#pragma unroll
                for (int nt = 0; nt < 4; nt++) {
                    mma_tf32(acc[mt][nt], ah0, ah1, ah2, ah3, bh[nt][0], bh[nt][1]);
                    mma_tf32(acc[mt][nt], ah0, ah1, ah2, ah3, bl[nt][0], bl[nt][1]);
                }
            }
        }
        __syncthreads();
    }

    // ---- write C ----
#pragma unroll
    for (int mt = 0; mt < 4; mt++) {
#pragma unroll
        for (int nt = 0; nt < 4; nt++) {
            int r = mBase + wm * 64 + mt * 16 + gid;
            int cc = nBase + wn * 32 + nt * 8 + 2 * tig;
            *(float2*)(C + (size_t)r * ODIM + cc) = make_float2(acc[mt][nt][0], acc[mt][nt][1]);
            *(float2*)(C + (size_t)(r + 8) * ODIM + cc) = make_float2(acc[mt][nt][2], acc[mt][nt][3]);
        }
    }

    // ---- epilogue: deterministic per-channel partial sum / sumsq ----
    float cs[4][2], cq[4][2];
#pragma unroll
    for (int nt = 0; nt < 4; nt++) {
#pragma unroll
        for (int e = 0; e < 2; e++) {
            float s = 0.0f, q = 0.0f;
#pragma unroll
            for (int mt = 0; mt < 4; mt++) {
                float v0 = acc[mt][nt][e], v1 = acc[mt][nt][e + 2];
                s += v0 + v1;
                q = fmaf(v0, v0, q);
                q = fmaf(v1, v1, q);
            }
            cs[nt][e] = s; cq[nt][e] = q;
        }
    }
#pragma unroll
    for (int nt = 0; nt < 4; nt++) {
#pragma unroll
        for (int e = 0; e < 2; e++) {
            float s = cs[nt][e], q = cq[nt][e];
            s += __shfl_xor_sync(0xFFFFFFFFu, s, 4);
            s += __shfl_xor_sync(0xFFFFFFFFu, s, 8);
            s += __shfl_xor_sync(0xFFFFFFFFu, s, 16);
            q += __shfl_xor_sync(0xFFFFFFFFu, q, 4);
            q += __shfl_xor_sync(0xFFFFFFFFu, q, 8);
            q += __shfl_xor_sync(0xFFFFFFFFu, q, 16);
            if (gid == 0) {
                int c = wn * 32 + nt * 8 + 2 * tig + e;
                sS[wm][c] = s;  sQ[wm][c] = q;
            }
        }
    }
    __syncthreads();
    if (tid < 128) {
        float s = sS[0][tid] + sS[1][tid];
        float q = sQ[0][tid] + sQ[1][tid];
        g_partM[LAYER][blockIdx.y][nBase + tid] = s;
        g_partM[LAYER][blockIdx.y][ODIM + nBase + tid] = q;
    }
}

// reduce per-mblock partials + compute per-channel scale/shift
__global__ void __launch_bounds__(512) stats_reduce_kernel(int layer,
                                                           const float* __restrict__ gamma,
                                                           const float* __restrict__ beta) {
    __shared__ float ssum[2 * ODIM];
    int t = threadIdx.x;
    float s = 0.0f;
    for (int r = 0; r < MBLK; r++) s += g_partM[layer][r][t];
    ssum[t] = s;
    __syncthreads();
    if (t < ODIM) {
        float mu  = ssum[t] * INVN;
        float var = fmaf(-mu, mu, ssum[ODIM + t] * INVN);
        float sc = gamma[t] * rsqrtf(var + BN_EPS);
        g_scale[layer][t] = sc;
        g_shift[layer][t] = fmaf(-mu, sc, beta[t]);
    }
}

// ---------------- BN apply (final layer, no ReLU), float4 elementwise ---------
__global__ void __launch_bounds__(256) bn_apply_kernel(float* __restrict__ Y, int layer) {
    int idx = blockIdx.x * blockDim.x + threadIdx.x;
    int e = idx * 4;
    int c = e & (ODIM - 1);
    float4 v = *(const float4*)(Y + e);
    float o[4] = {v.x, v.y, v.z, v.w};
#pragma unroll
    for (int j = 0; j < 4; j++) {
        int ch = c + j;
        o[j] = fmaf(o[j], g_scale[layer][ch], g_shift[layer][ch]);
    }
    *(float4*)(Y + e) = make_float4(o[0], o[1], o[2], o[3]);
}

// ---------------- launcher ----------------------------------------------------
extern "C" void kernel_launch(void* const* d_in, const int* in_sizes, int n_in,
                              void* d_out, int out_size) {
    const float* x   = (const float*)d_in[0];   // [8,2048,128]
    const float* pos = (const float*)d_in[1];   // [8,2048,3]
    const float* W1  = (const float*)d_in[2];   // [131,256]
    // d_in[3] = b1 (cancels under train-mode BN)
    const float* g1  = (const float*)d_in[4];
    const float* be1 = (const float*)d_in[5];
    const float* W2  = (const float*)d_in[6];   // [256,256]
    // d_in[7] = b2 (cancels)
    const float* g2  = (const float*)d_in[8];
    const float* be2 = (const float*)d_in[9];
    float* out = (float*)d_out;                 // [8,2048,256]

    prep_kernel<<<KPAD, ODIM>>>(W1);
    knn_kernel<<<BATCH * (NPTS / 32), 64>>>(pos);
    gather_avg_kernel<<<ROWS, 128>>>(x, pos);

    float* avg = nullptr; float* w1p = nullptr; float* c1 = nullptr;
    cudaGetSymbolAddress((void**)&avg, g_avg);
    cudaGetSymbolAddress((void**)&w1p, g_w1p);
    cudaGetSymbolAddress((void**)&c1,  g_c1);

    dim3 ggrid(ODIM / 128, ROWS / 128);         // (2, 128)
    gemm_tc<false, 0><<<ggrid, 256>>>(avg, KPAD, KPAD, w1p, c1);
    stats_reduce_kernel<<<1, 512>>>(0, g1, be1);

    // layer-2 GEMM with BN1+ReLU fused into A staging; stats fused in epilogue
    gemm_tc<true, 1><<<ggrid, 256>>>(c1, ODIM, ODIM, W2, out);
    stats_reduce_kernel<<<1, 512>>>(1, g2, be2);
    bn_apply_kernel<<<ROWS * ODIM / 4 / 256, 256>>>(out, 1);
}